// round 4
// baseline (speedup 1.0000x reference)
#include <cuda_runtime.h>
#include <cuda_bf16.h>
#include <math.h>
#include <stdint.h>

#define B_ 4
#define N_ 1024
#define HW_ 4096
#define D_ 512
#define H_ 8
#define DK_ 64
#define ZTOT (B_ * H_)
#define ROWS_TOT (ZTOT * N_)
#define STILES (HW_ / 128)

// ---------------- scratch (static device globals; no allocation) -----------
__device__ __nv_bfloat16 g_qh[B_ * N_ * D_],  g_ql[B_ * N_ * D_];
__device__ __nv_bfloat16 g_kh[B_ * HW_ * D_], g_kl[B_ * HW_ * D_];
__device__ __nv_bfloat16 g_vh[B_ * HW_ * D_], g_vl[B_ * HW_ * D_];
__device__ __nv_bfloat16 g_wqh[D_ * D_], g_wql[D_ * D_];
__device__ __nv_bfloat16 g_wkh[D_ * D_], g_wkl[D_ * D_];
__device__ __nv_bfloat16 g_wvh[D_ * D_], g_wvl[D_ * D_];
__device__ __nv_bfloat16 g_woh[D_ * D_], g_wol[D_ * D_];
__device__ __nv_bfloat16 g_Qh[B_ * N_ * D_],  g_Ql[B_ * N_ * D_];
__device__ __nv_bfloat16 g_Kh[B_ * HW_ * D_], g_Kl[B_ * HW_ * D_];
__device__ __nv_bfloat16 g_Vh[B_ * HW_ * D_], g_Vl[B_ * HW_ * D_];
__device__ __nv_bfloat16 g_ctxh[B_ * N_ * D_], g_ctxl[B_ * N_ * D_];
__device__ unsigned char g_mask[N_ * HW_];
__device__ float g_statm[(size_t)ROWS_TOT * STILES];
__device__ float g_stats_[(size_t)ROWS_TOT * STILES];
__device__ float g_rm[ROWS_TOT];
__device__ float g_ri[ROWS_TOT];

// ---------------- helpers --------------------------------------------------
__device__ __forceinline__ uint32_t smem_u32(const void* p) {
    return (uint32_t)__cvta_generic_to_shared(p);
}
__device__ __forceinline__ void cp16(uint32_t s, const void* g) {
    asm volatile("cp.async.cg.shared.global [%0],[%1],16;" :: "r"(s), "l"(g));
}
__device__ __forceinline__ void cp_commit() {
    asm volatile("cp.async.commit_group;" ::: "memory");
}
template <int NN>
__device__ __forceinline__ void cp_wait() {
    asm volatile("cp.async.wait_group %0;" :: "n"(NN) : "memory");
}
__device__ __forceinline__ void ldsm4(uint32_t& r0, uint32_t& r1, uint32_t& r2,
                                      uint32_t& r3, uint32_t a) {
    asm volatile("ldmatrix.sync.aligned.m8n8.x4.shared.b16 {%0,%1,%2,%3},[%4];"
                 : "=r"(r0), "=r"(r1), "=r"(r2), "=r"(r3) : "r"(a));
}
__device__ __forceinline__ void ldsm4t(uint32_t& r0, uint32_t& r1, uint32_t& r2,
                                       uint32_t& r3, uint32_t a) {
    asm volatile("ldmatrix.sync.aligned.m8n8.x4.trans.shared.b16 {%0,%1,%2,%3},[%4];"
                 : "=r"(r0), "=r"(r1), "=r"(r2), "=r"(r3) : "r"(a));
}
__device__ __forceinline__ void mma_bf16(float* c, const uint32_t* a, const uint32_t* b) {
    asm volatile(
        "mma.sync.aligned.m16n8k16.row.col.f32.bf16.bf16.f32 "
        "{%0,%1,%2,%3},{%4,%5,%6,%7},{%8,%9},{%0,%1,%2,%3};"
        : "+f"(c[0]), "+f"(c[1]), "+f"(c[2]), "+f"(c[3])
        : "r"(a[0]), "r"(a[1]), "r"(a[2]), "r"(a[3]), "r"(b[0]), "r"(b[1]));
}
__device__ __forceinline__ void split2(float x, float y, uint32_t& hi, uint32_t& lo) {
    __nv_bfloat16 hx = __float2bfloat16(x);
    __nv_bfloat16 hy = __float2bfloat16(y);
    __nv_bfloat16 lx = __float2bfloat16(x - __bfloat162float(hx));
    __nv_bfloat16 ly = __float2bfloat16(y - __bfloat162float(hy));
    hi = (uint32_t)__bfloat16_as_ushort(hx) | ((uint32_t)__bfloat16_as_ushort(hy) << 16);
    lo = (uint32_t)__bfloat16_as_ushort(lx) | ((uint32_t)__bfloat16_as_ushort(ly) << 16);
}
// online softmax-stat update
__device__ __forceinline__ void stat_upd(float& m, float& s, float v) {
    if (v > m) { s *= __expf(m - v); m = v; }
    s += __expf(v - m);
}

// ---------------- split fp32 -> hi/lo bf16 ---------------------------------
__global__ void split_kernel(const float4* __restrict__ X, uint2* __restrict__ Xh,
                             uint2* __restrict__ Xl, int n4) {
    int i = blockIdx.x * blockDim.x + threadIdx.x;
    if (i >= n4) return;
    float4 v = X[i];
    uint32_t h0, l0, h1, l1;
    split2(v.x, v.y, h0, l0);
    split2(v.z, v.w, h1, l1);
    Xh[i] = make_uint2(h0, h1);
    Xl[i] = make_uint2(l0, l1);
}

// ---------------- mask precompute ------------------------------------------
__global__ void mask_kernel(const float* __restrict__ x_tilde,
                            const float* __restrict__ x_hat,
                            unsigned char* __restrict__ mask) {
    int idx = blockIdx.x * blockDim.x + threadIdx.x;
    if (idx >= N_ * HW_) return;
    int m = idx & (HW_ - 1);
    float dx = x_tilde[m * 2 + 0] - x_hat[(size_t)idx * 2 + 0];
    float dy = x_tilde[m * 2 + 1] - x_hat[(size_t)idx * 2 + 1];
    mask[idx] = (sqrtf(dx * dx + dy * dy) < 0.1f) ? 1 : 0;
}

// ---------------- pipelined split-bf16 MMA GEMM ----------------------------
// C = alpha * (A @ B^T) + bias. A,B pre-split hi/lo bf16.
// SPLITOUT: write hi/lo bf16. SCORES: mask to -1e30 + per-tile softmax stats.
template <int BM, int BN, int BK, int WM, int WN, bool SPLITOUT, bool SCORES>
__global__ void __launch_bounds__(256) gemm_bf16(
    const __nv_bfloat16* __restrict__ Agh, const __nv_bfloat16* __restrict__ Agl,
    const __nv_bfloat16* __restrict__ Bgh, const __nv_bfloat16* __restrict__ Bgl,
    const float* __restrict__ bias, float* __restrict__ C,
    __nv_bfloat16* __restrict__ Ch, __nv_bfloat16* __restrict__ Cl,
    int K, int lda, int ldb, int ldc,
    long sAb, long sAh0, long sBb, long sBh0, long sCb, long sCh0, float alpha,
    const unsigned char* __restrict__ maskp,
    float* __restrict__ statm, float* __restrict__ stats_) {
    constexpr int STAGES = 3;
    constexpr int SA = BK + 8;
    constexpr int SB = BK + 8;
    constexpr int ASZ = BM * SA;
    constexpr int BSZ = BN * SB;
    constexpr int STRIDE = 2 * ASZ + 2 * BSZ;
    extern __shared__ __nv_bfloat16 smem[];

    int z = blockIdx.z;
    int zb = z >> 3, zh = z & 7;
    Agh += zb * sAb + zh * sAh0;
    Agl += zb * sAb + zh * sAh0;
    Bgh += zb * sBb + zh * sBh0;
    Bgl += zb * sBb + zh * sBh0;
    long coff = zb * sCb + zh * sCh0;

    int m0 = blockIdx.y * BM;
    int n0 = blockIdx.x * BN;
    int tid = threadIdx.x;
    int lane = tid & 31;
    int wid = tid >> 5;
    constexpr int WNC = BN / WN;
    int wm0 = (wid / WNC) * WM;
    int wn0 = (wid % WNC) * WN;
    constexpr int MT = WM / 16;
    constexpr int NT = WN / 8;
    constexpr int NTP = NT / 2;

    int nK = K / BK;
    uint32_t smem_b = smem_u32(smem);

    auto issue = [&](int kc) {
        int s = kc % STAGES;
        int k0 = kc * BK;
        uint32_t base = smem_b + (uint32_t)(s * STRIDE) * 2;
        for (int i = tid; i < BM * (BK / 8); i += 256) {
            int r = i / (BK / 8);
            int c = (i % (BK / 8)) * 8;
            long go = (long)(m0 + r) * lda + k0 + c;
            uint32_t so = (uint32_t)(r * SA + c) * 2;
            cp16(base + so, Agh + go);
            cp16(base + (uint32_t)ASZ * 2 + so, Agl + go);
        }
        uint32_t bb = base + (uint32_t)(2 * ASZ) * 2;
        for (int i = tid; i < BN * (BK / 8); i += 256) {
            int r = i / (BK / 8);
            int c = (i % (BK / 8)) * 8;
            long go = (long)(n0 + r) * ldb + k0 + c;
            uint32_t so = (uint32_t)(r * SB + c) * 2;
            cp16(bb + so, Bgh + go);
            cp16(bb + (uint32_t)BSZ * 2 + so, Bgl + go);
        }
    };

    float acc[MT][NT][4];
#pragma unroll
    for (int i = 0; i < MT; i++)
#pragma unroll
        for (int j = 0; j < NT; j++)
#pragma unroll
            for (int q = 0; q < 4; q++) acc[i][j][q] = 0.0f;

    for (int s = 0; s < STAGES - 1; s++) {
        if (s < nK) issue(s);
        cp_commit();
    }

    for (int kc = 0; kc < nK; kc++) {
        int pf = kc + STAGES - 1;
        if (pf < nK) issue(pf);
        cp_commit();
        cp_wait<STAGES - 1>();
        __syncthreads();

        int s = kc % STAGES;
        const __nv_bfloat16* Ah_s = smem + s * STRIDE;
        const __nv_bfloat16* Al_s = Ah_s + ASZ;
        const __nv_bfloat16* Bh_s = Ah_s + 2 * ASZ;
        const __nv_bfloat16* Bl_s = Bh_s + BSZ;

#pragma unroll
        for (int ks = 0; ks < BK / 16; ks++) {
            uint32_t af[MT][4], al_[MT][4];
#pragma unroll
            for (int mt = 0; mt < MT; mt++) {
                int row = wm0 + mt * 16 + (lane & 15);
                int col = ks * 16 + (lane >> 4) * 8;
                ldsm4(af[mt][0], af[mt][1], af[mt][2], af[mt][3],
                      smem_u32(&Ah_s[row * SA + col]));
                ldsm4(al_[mt][0], al_[mt][1], al_[mt][2], al_[mt][3],
                      smem_u32(&Al_s[row * SA + col]));
            }
            uint32_t bfr[NT][2], blr[NT][2];
#pragma unroll
            for (int ntp = 0; ntp < NTP; ntp++) {
                int g = lane >> 3;
                int noff = (g >> 1) * 8;
                int koff = (g & 1) * 8;
                uint32_t r0, r1, r2, r3;
                int row = wn0 + ntp * 16 + noff + (lane & 7);
                int col = ks * 16 + koff;
                ldsm4(r0, r1, r2, r3, smem_u32(&Bh_s[row * SB + col]));
                bfr[2 * ntp][0] = r0; bfr[2 * ntp][1] = r1;
                bfr[2 * ntp + 1][0] = r2; bfr[2 * ntp + 1][1] = r3;
                ldsm4(r0, r1, r2, r3, smem_u32(&Bl_s[row * SB + col]));
                blr[2 * ntp][0] = r0; blr[2 * ntp][1] = r1;
                blr[2 * ntp + 1][0] = r2; blr[2 * ntp + 1][1] = r3;
            }
#pragma unroll
            for (int mt = 0; mt < MT; mt++)
#pragma unroll
                for (int nt = 0; nt < NT; nt++) {
                    mma_bf16(acc[mt][nt], af[mt], bfr[nt]);
                    mma_bf16(acc[mt][nt], af[mt], blr[nt]);
                    mma_bf16(acc[mt][nt], al_[mt], bfr[nt]);
                }
        }
        __syncthreads();
    }

    // ---- epilogue ----
    if constexpr (SCORES) {
        // masked write + per-row online (max, sumexp) for this BN-wide tile
        float rm_[2 * MT], rs_[2 * MT];
#pragma unroll
        for (int i = 0; i < 2 * MT; i++) { rm_[i] = -1e30f; rs_[i] = 0.0f; }
#pragma unroll
        for (int mt = 0; mt < MT; mt++)
#pragma unroll
            for (int nt = 0; nt < NT; nt++) {
                int row = m0 + wm0 + mt * 16 + (lane >> 2);
                int col = n0 + wn0 + nt * 8 + (lane & 3) * 2;
                const unsigned char* mrow = maskp + (long)row * HW_ + col;
                float v0x = mrow[0] ? acc[mt][nt][0] * alpha : -1e30f;
                float v0y = mrow[1] ? acc[mt][nt][1] * alpha : -1e30f;
                const unsigned char* mrow8 = mrow + 8 * HW_;
                float v1x = mrow8[0] ? acc[mt][nt][2] * alpha : -1e30f;
                float v1y = mrow8[1] ? acc[mt][nt][3] * alpha : -1e30f;
                *(float2*)&C[coff + (long)row * ldc + col] = make_float2(v0x, v0y);
                *(float2*)&C[coff + (long)(row + 8) * ldc + col] = make_float2(v1x, v1y);
                stat_upd(rm_[2 * mt], rs_[2 * mt], v0x);
                stat_upd(rm_[2 * mt], rs_[2 * mt], v0y);
                stat_upd(rm_[2 * mt + 1], rs_[2 * mt + 1], v1x);
                stat_upd(rm_[2 * mt + 1], rs_[2 * mt + 1], v1y);
            }
        // reduce over the 4 lanes sharing a row (lane&3)
#pragma unroll
        for (int i = 0; i < 2 * MT; i++) {
#pragma unroll
            for (int o = 1; o <= 2; o <<= 1) {
                float mo = __shfl_xor_sync(0xffffffffu, rm_[i], o);
                float so = __shfl_xor_sync(0xffffffffu, rs_[i], o);
                float mn = fmaxf(rm_[i], mo);
                rs_[i] = rs_[i] * __expf(rm_[i] - mn) + so * __expf(mo - mn);
                rm_[i] = mn;
            }
        }
        // ensure any in-flight cp.async prefetches are done before smem reuse
        cp_wait<0>();
        __syncthreads();
        float* stm = (float*)smem;            // [BM][WNC]
        float* sts = stm + BM * WNC;
        if ((lane & 3) == 0) {
            int grp = wid % WNC;
#pragma unroll
            for (int mt = 0; mt < MT; mt++) {
                int lr0 = wm0 + mt * 16 + (lane >> 2);
                stm[lr0 * WNC + grp] = rm_[2 * mt];
                sts[lr0 * WNC + grp] = rs_[2 * mt];
                stm[(lr0 + 8) * WNC + grp] = rm_[2 * mt + 1];
                sts[(lr0 + 8) * WNC + grp] = rs_[2 * mt + 1];
            }
        }
        __syncthreads();
        if (tid < BM) {
            float m = -1e30f, ss = 0.0f;
#pragma unroll
            for (int g = 0; g < WNC; g++) {
                float mo = stm[tid * WNC + g];
                float so = sts[tid * WNC + g];
                float mn = fmaxf(m, mo);
                ss = ss * __expf(m - mn) + so * __expf(mo - mn);
                m = mn;
            }
            long sidx = ((long)z * N_ + m0 + tid) * STILES + blockIdx.x;
            statm[sidx] = m;
            stats_[sidx] = ss;
        }
    } else {
#pragma unroll
        for (int mt = 0; mt < MT; mt++)
#pragma unroll
            for (int nt = 0; nt < NT; nt++) {
                int row = m0 + wm0 + mt * 16 + (lane >> 2);
                int col = n0 + wn0 + nt * 8 + (lane & 3) * 2;
                float bx = 0.f, by = 0.f;
                if (bias) { bx = bias[col]; by = bias[col + 1]; }
                float v0x = acc[mt][nt][0] * alpha + bx;
                float v0y = acc[mt][nt][1] * alpha + by;
                float v1x = acc[mt][nt][2] * alpha + bx;
                float v1y = acc[mt][nt][3] * alpha + by;
                if constexpr (SPLITOUT) {
                    uint32_t hh, ll;
                    split2(v0x, v0y, hh, ll);
                    *(uint32_t*)&Ch[coff + (long)row * ldc + col] = hh;
                    *(uint32_t*)&Cl[coff + (long)row * ldc + col] = ll;
                    split2(v1x, v1y, hh, ll);
                    *(uint32_t*)&Ch[coff + (long)(row + 8) * ldc + col] = hh;
                    *(uint32_t*)&Cl[coff + (long)(row + 8) * ldc + col] = ll;
                } else {
                    *(float2*)&C[coff + (long)row * ldc + col] = make_float2(v0x, v0y);
                    *(float2*)&C[coff + (long)(row + 8) * ldc + col] = make_float2(v1x, v1y);
                }
            }
    }
}

// ---------------- combine per-tile stats -> per-row (max, 1/sum) -----------
__global__ void stats_combine(const float* __restrict__ statm,
                              const float* __restrict__ stats_,
                              float* __restrict__ rm, float* __restrict__ ri) {
    int i = blockIdx.x * blockDim.x + threadIdx.x;
    if (i >= ROWS_TOT) return;
    const float* pm = statm + (long)i * STILES;
    const float* ps = stats_ + (long)i * STILES;
    float m = -1e30f, s = 0.0f;
#pragma unroll 8
    for (int t = 0; t < STILES; t++) {
        float mo = pm[t], so = ps[t];
        float mn = fmaxf(m, mo);
        s = s * __expf(m - mn) + so * __expf(mo - mn);
        m = mn;
    }
    rm[i] = m;
    ri[i] = 1.0f / s;
}

// ---------------- fused softmax-normalize + P@V ----------------------------
// Per block: one (b,h), 128 query rows. Single pass over S (in attn buffer):
// P = exp(s-m)*inv -> written back as attn output, split bf16 -> smem, MMA vs V.
#define FPAD 136
#define VPAD 72
__global__ void __launch_bounds__(256, 2) fused_pv(
    float* __restrict__ attn,
    const __nv_bfloat16* __restrict__ Vh, const __nv_bfloat16* __restrict__ Vl,
    __nv_bfloat16* __restrict__ Ch, __nv_bfloat16* __restrict__ Cl,
    const float* __restrict__ rm, const float* __restrict__ ri) {
    extern __shared__ __nv_bfloat16 sm[];
    __nv_bfloat16* Phs = sm;                       // 128*FPAD
    __nv_bfloat16* Pls = Phs + 128 * FPAD;
    __nv_bfloat16* Vhs = Pls + 128 * FPAD;         // 128*VPAD
    __nv_bfloat16* Vls = Vhs + 128 * VPAD;
    float* rmx = (float*)(Vls + 128 * VPAD);       // 128
    float* rin = rmx + 128;

    int z = blockIdx.y;
    int b = z >> 3, h = z & 7;
    int n0 = blockIdx.x * 128;
    int tid = threadIdx.x;
    int lane = tid & 31;
    int w = tid >> 5;

    if (tid < 128) {
        long ridx = (long)z * N_ + n0 + tid;
        rmx[tid] = rm[ridx];
        rin[tid] = ri[ridx];
    }
    __syncthreads();

    float* S = attn + ((long)z * N_ + n0) * HW_;
    const __nv_bfloat16* Vbh = Vh + (long)b * HW_ * D_ + h * DK_;
    const __nv_bfloat16* Vbl = Vl + (long)b * HW_ * D_ + h * DK_;

    int wm0 = (w >> 1) * 32;
    int wn0 = (w & 1) * 32;
    float acc[2][4][4];
#pragma unroll
    for (int i = 0; i < 2; i++)
#pragma unroll
        for (int j = 0; j < 4; j++)
#pragma unroll
            for (int q = 0; q < 4; q++) acc[i][j][q] = 0.0f;

    for (int mc = 0; mc < HW_; mc += 128) {
        // stage V chunk (rows mc..mc+127 of V, 64 dk cols, hi/lo)
        for (int i = tid; i < 128 * 8; i += 256) {
            int r = i >> 3;
            int cc = (i & 7) * 8;
            long go = (long)(mc + r) * D_ + cc;
            cp16(smem_u32(&Vhs[r * VPAD + cc]), Vbh + go);
            cp16(smem_u32(&Vls[r * VPAD + cc]), Vbl + go);
        }
        cp_commit();

        // P chunk: warp w owns rows {k*8+w}; 1 float4/lane covers 128 cols
#pragma unroll 4
        for (int k = 0; k < 16; k++) {
            int r = k * 8 + w;
            float m = rmx[r], inv = rin[r];
            float* rp = S + (long)r * HW_ + mc + lane * 4;
            float4 v = *(const float4*)rp;
            float4 p;
            p.x = __expf(v.x - m) * inv;
            p.y = __expf(v.y - m) * inv;
            p.z = __expf(v.z - m) * inv;
            p.w = __expf(v.w - m) * inv;
            *(float4*)rp = p;  // normalized attn output (in place)
            uint32_t h0, l0, h1, l1;
            split2(p.x, p.y, h0, l0);
            split2(p.z, p.w, h1, l1);
            *(uint2*)&Phs[r * FPAD + lane * 4] = make_uint2(h0, h1);
            *(uint2*)&Pls[r * FPAD + lane * 4] = make_uint2(l0, l1);
        }
        cp_wait<0>();
        __syncthreads();

        // MMA: ctx[128,64] += P[128,128] @ V[128,64]
#pragma unroll
        for (int ks = 0; ks < 8; ks++) {
            uint32_t af[2][4], al_[2][4];
#pragma unroll
            for (int mt = 0; mt < 2; mt++) {
                int row = wm0 + mt * 16 + (lane & 15);
                int col = ks * 16 + (lane >> 4) * 8;
                ldsm4(af[mt][0], af[mt][1], af[mt][2], af[mt][3],
                      smem_u32(&Phs[row * FPAD + col]));
                ldsm4(al_[mt][0], al_[mt][1], al_[mt][2], al_[mt][3],
                      smem_u32(&Pls[row * FPAD + col]));
            }
            uint32_t bh_[4][2], bl_[4][2];
#pragma unroll
            for (int ntp = 0; ntp < 2; ntp++) {
                int g = lane >> 3;
                int noff = (g >> 1) * 8;
                int koff = (g & 1) * 8;
                int row = ks * 16 + koff + (lane & 7);
                int col = wn0 + ntp * 16 + noff;
                uint32_t r0, r1, r2, r3;
                ldsm4t(r0, r1, r2, r3, smem_u32(&Vhs[row * VPAD + col]));
                bh_[2 * ntp][0] = r0; bh_[2 * ntp][1] = r1;
                bh_[2 * ntp + 1][0] = r2; bh_[2 * ntp + 1][1] = r3;
                ldsm4t(r0, r1, r2, r3, smem_u32(&Vls[row * VPAD + col]));
                bl_[2 * ntp][0] = r0; bl_[2 * ntp][1] = r1;
                bl_[2 * ntp + 1][0] = r2; bl_[2 * ntp + 1][1] = r3;
            }
#pragma unroll
            for (int mt = 0; mt < 2; mt++)
#pragma unroll
                for (int nt = 0; nt < 4; nt++) {
                    mma_bf16(acc[mt][nt], af[mt], bh_[nt]);
                    mma_bf16(acc[mt][nt], af[mt], bl_[nt]);
                    mma_bf16(acc[mt][nt], al_[mt], bh_[nt]);
                }
        }
        __syncthreads();
    }

    // ctx epilogue -> split bf16
#pragma unroll
    for (int mt = 0; mt < 2; mt++)
#pragma unroll
        for (int nt = 0; nt < 4; nt++) {
            int row = wm0 + mt * 16 + (lane >> 2);
            int col = wn0 + nt * 8 + (lane & 3) * 2;
            long off = ((long)b * N_ + n0 + row) * D_ + h * DK_ + col;
            uint32_t hh, ll;
            split2(acc[mt][nt][0], acc[mt][nt][1], hh, ll);
            *(uint32_t*)&Ch[off] = hh;
            *(uint32_t*)&Cl[off] = ll;
            split2(acc[mt][nt][2], acc[mt][nt][3], hh, ll);
            *(uint32_t*)&Ch[off + 8 * D_] = hh;
            *(uint32_t*)&Cl[off + 8 * D_] = ll;
        }
}

// ---------------- launch ---------------------------------------------------
extern "C" void kernel_launch(void* const* d_in, const int* in_sizes, int n_in,
                              void* d_out, int out_size) {
    const float* query   = (const float*)d_in[0];
    const float* key     = (const float*)d_in[1];
    const float* value   = (const float*)d_in[2];
    const float* x_tilde = (const float*)d_in[3];
    const float* x_hat   = (const float*)d_in[4];
    const float* Wq = (const float*)d_in[5];
    const float* bq = (const float*)d_in[6];
    const float* Wk = (const float*)d_in[7];
    const float* bk = (const float*)d_in[8];
    const float* Wv = (const float*)d_in[9];
    const float* bv = (const float*)d_in[10];
    const float* Wo = (const float*)d_in[11];
    const float* bo = (const float*)d_in[12];

    float* out = (float*)d_out;
    float* attn = out + (size_t)B_ * N_ * D_;

    __nv_bfloat16 *qh, *ql, *kh, *kl, *vh, *vl;
    __nv_bfloat16 *wqh, *wql, *wkh, *wkl, *wvh, *wvl, *woh, *wol;
    __nv_bfloat16 *Qh, *Ql, *Kh, *Kl, *Vh, *Vl, *ch, *cl;
    unsigned char* Mp;
    float *stm, *sts, *rmp, *rip;
    cudaGetSymbolAddress((void**)&qh, g_qh);   cudaGetSymbolAddress((void**)&ql, g_ql);
    cudaGetSymbolAddress((void**)&kh, g_kh);   cudaGetSymbolAddress((void**)&kl, g_kl);
    cudaGetSymbolAddress((void**)&vh, g_vh);   cudaGetSymbolAddress((void**)&vl, g_vl);
    cudaGetSymbolAddress((void**)&wqh, g_wqh); cudaGetSymbolAddress((void**)&wql, g_wql);
    cudaGetSymbolAddress((void**)&wkh, g_wkh); cudaGetSymbolAddress((void**)&wkl, g_wkl);
    cudaGetSymbolAddress((void**)&wvh, g_wvh); cudaGetSymbolAddress((void**)&wvl, g_wvl);
    cudaGetSymbolAddress((void**)&woh, g_woh); cudaGetSymbolAddress((void**)&wol, g_wol);
    cudaGetSymbolAddress((void**)&Qh, g_Qh);   cudaGetSymbolAddress((void**)&Ql, g_Ql);
    cudaGetSymbolAddress((void**)&Kh, g_Kh);   cudaGetSymbolAddress((void**)&Kl, g_Kl);
    cudaGetSymbolAddress((void**)&Vh, g_Vh);   cudaGetSymbolAddress((void**)&Vl, g_Vl);
    cudaGetSymbolAddress((void**)&ch, g_ctxh); cudaGetSymbolAddress((void**)&cl, g_ctxl);
    cudaGetSymbolAddress((void**)&Mp, g_mask);
    cudaGetSymbolAddress((void**)&stm, g_statm);
    cudaGetSymbolAddress((void**)&sts, g_stats_);
    cudaGetSymbolAddress((void**)&rmp, g_rm);
    cudaGetSymbolAddress((void**)&rip, g_ri);

    mask_kernel<<<(N_ * HW_ + 255) / 256, 256>>>(x_tilde, x_hat, Mp);

    split_kernel<<<(B_ * N_ * D_ / 4 + 255) / 256, 256>>>(
        (const float4*)query, (uint2*)qh, (uint2*)ql, B_ * N_ * D_ / 4);
    split_kernel<<<(B_ * HW_ * D_ / 4 + 255) / 256, 256>>>(
        (const float4*)key, (uint2*)kh, (uint2*)kl, B_ * HW_ * D_ / 4);
    split_kernel<<<(B_ * HW_ * D_ / 4 + 255) / 256, 256>>>(
        (const float4*)value, (uint2*)vh, (uint2*)vl, B_ * HW_ * D_ / 4);
    split_kernel<<<(D_ * D_ / 4 + 255) / 256, 256>>>(
        (const float4*)Wq, (uint2*)wqh, (uint2*)wql, D_ * D_ / 4);
    split_kernel<<<(D_ * D_ / 4 + 255) / 256, 256>>>(
        (const float4*)Wk, (uint2*)wkh, (uint2*)wkl, D_ * D_ / 4);
    split_kernel<<<(D_ * D_ / 4 + 255) / 256, 256>>>(
        (const float4*)Wv, (uint2*)wvh, (uint2*)wvl, D_ * D_ / 4);
    split_kernel<<<(D_ * D_ / 4 + 255) / 256, 256>>>(
        (const float4*)Wo, (uint2*)woh, (uint2*)wol, D_ * D_ / 4);

    constexpr int SMEM_BIG = 3 * (2 * 128 * 40 + 2 * 128 * 40) * 2;  // 122880
    constexpr int SMEM_FUSED = (2 * 128 * FPAD + 2 * 128 * VPAD) * 2 + 2 * 128 * 4 + 256;

    auto* kProj   = gemm_bf16<128, 128, 32, 64, 32, true, false>;
    auto* kScores = gemm_bf16<128, 128, 32, 64, 32, false, true>;
    auto* kOut    = gemm_bf16<128, 128, 32, 64, 32, false, false>;
    cudaFuncSetAttribute(kProj, cudaFuncAttributeMaxDynamicSharedMemorySize, SMEM_BIG);
    cudaFuncSetAttribute(kScores, cudaFuncAttributeMaxDynamicSharedMemorySize, SMEM_BIG);
    cudaFuncSetAttribute(kOut, cudaFuncAttributeMaxDynamicSharedMemorySize, SMEM_BIG);
    cudaFuncSetAttribute(fused_pv, cudaFuncAttributeMaxDynamicSharedMemorySize, SMEM_FUSED);

    // projections -> split bf16
    kProj<<<dim3(4, 32, 1), 256, SMEM_BIG>>>(qh, ql, wqh, wql, bq, nullptr, Qh, Ql,
                                             D_, D_, D_, D_, 0, 0, 0, 0, 0, 0, 1.0f,
                                             nullptr, nullptr, nullptr);
    kProj<<<dim3(4, 128, 1), 256, SMEM_BIG>>>(kh, kl, wkh, wkl, bk, nullptr, Kh, Kl,
                                              D_, D_, D_, D_, 0, 0, 0, 0, 0, 0, 1.0f,
                                              nullptr, nullptr, nullptr);
    kProj<<<dim3(4, 128, 1), 256, SMEM_BIG>>>(vh, vl, wvh, wvl, bv, nullptr, Vh, Vl,
                                              D_, D_, D_, D_, 0, 0, 0, 0, 0, 0, 1.0f,
                                              nullptr, nullptr, nullptr);

    // scores: masked raw S into attn buffer + per-tile softmax stats
    kScores<<<dim3(32, 8, 32), 256, SMEM_BIG>>>(
        Qh, Ql, Kh, Kl, nullptr, attn, nullptr, nullptr,
        DK_, D_, D_, HW_,
        (long)N_ * D_, DK_, (long)HW_ * D_, DK_,
        (long)H_ * N_ * HW_, (long)N_ * HW_, 0.125f,
        Mp, stm, sts);

    stats_combine<<<(ROWS_TOT + 255) / 256, 256>>>(stm, sts, rmp, rip);

    // fused: normalize + write attn + ctx = P@V (split bf16 out)
    fused_pv<<<dim3(8, 32), 256, SMEM_FUSED>>>(attn, Vh, Vl, ch, cl, rmp, rip);

    // out projection -> fp32
    kOut<<<dim3(4, 32, 1), 256, SMEM_BIG>>>(
        ch, cl, woh, wol, bo, out, nullptr, nullptr,
        D_, D_, D_, D_, 0, 0, 0, 0, 0, 0, 1.0f,
        nullptr, nullptr, nullptr);
}